// round 10
// baseline (speedup 1.0000x reference)
#include <cuda_runtime.h>
#include <math.h>

#define BB 32
#define TL 256
#define DL 512
#define HH 512
#define VV 2000
#define MM 256
#define G4 2048
#define XD 2512
#define NSTEP 100

#define S_P0 8           // gates0 slots: 6 (Wih0) + 2 (Whh0)
#define CH_IH0 419       // ceil(2512/6)
#define LD 2048          // row stride inside partial buffers

// ---------------- persistent device state ----------------
__device__ float g_x[BB * XD];
__device__ float g_h0[BB * HH], g_h1[BB * HH];
__device__ float g_c0a[BB * HH], g_c0b[BB * HH];   // ping-pong
__device__ float g_c1[BB * HH];
__device__ float g_ctx[BB * HH];
__device__ float g_p0[(size_t)S_P0 * BB * LD];     // [s][b][r]
__device__ float g_p1w[(size_t)2 * BB * LD];       // Whh1@h1_prev partials [s][b][r]
__device__ float g_pl[(size_t)4 * BB * LD];        // logits partials [s][b][v]
__device__ float g_clisT[(size_t)BB * MM * TL];    // [b][m][t]

__device__ __forceinline__ float sigmoidf_(float x) { return 1.f / (1.f + expf(-x)); }

// ---------------------------------------------------------------------------
// init: x0 = [onehot(0), listener[:,0,:]]; zero states
// ---------------------------------------------------------------------------
__global__ void k_init(const float* __restrict__ lis) {
    int i = blockIdx.x * blockDim.x + threadIdx.x;
    if (i < BB * XD) {
        int b = i / XD, k = i % XD;
        float v = 0.f;
        if (k == 0) v = 1.f;
        else if (k >= VV) v = lis[(size_t)b * TL * DL + (k - VV)];
        g_x[i] = v;
    }
    if (i < BB * HH) {
        g_h0[i] = 0.f; g_h1[i] = 0.f;
        g_c0a[i] = 0.f; g_c0b[i] = 0.f; g_c1[i] = 0.f;
    }
}

// ---------------------------------------------------------------------------
// one-time psi (R2-proven): clisT[b][m][t] = relu(lis[b][t].Wpsi[m]+bpsi[m])
// grid (8,4,32), 128 threads
// ---------------------------------------------------------------------------
__global__ void k_psi(const float* __restrict__ lis,
                      const float* __restrict__ Wpsi,
                      const float* __restrict__ bpsi) {
    int mb = blockIdx.x, tb = blockIdx.y, b = blockIdx.z;
    int tid = threadIdx.x;
    int mg = tid >> 4, tg = tid & 15;
    __shared__ float Ws[32 * 33];
    __shared__ float Ls[64 * 33];
    float acc[4][4] = {};
    const float* lb = lis + (size_t)b * TL * DL;
    for (int kc = 0; kc < DL; kc += 32) {
#pragma unroll
        for (int i = 0; i < 8; i++) {
            int lin = tid + i * 128;
            int row = lin >> 5, kk = lin & 31;
            Ws[row * 33 + kk] = Wpsi[(size_t)(mb * 32 + row) * DL + kc + kk];
        }
#pragma unroll
        for (int i = 0; i < 16; i++) {
            int lin = tid + i * 128;
            int row = lin >> 5, kk = lin & 31;
            Ls[row * 33 + kk] = lb[(size_t)(tb * 64 + row) * DL + kc + kk];
        }
        __syncthreads();
#pragma unroll 8
        for (int kk = 0; kk < 32; kk++) {
            float wv[4], lv[4];
#pragma unroll
            for (int i = 0; i < 4; i++) wv[i] = Ws[(mg * 4 + i) * 33 + kk];
#pragma unroll
            for (int j = 0; j < 4; j++) lv[j] = Ls[(tg * 4 + j) * 33 + kk];
#pragma unroll
            for (int i = 0; i < 4; i++)
#pragma unroll
                for (int j = 0; j < 4; j++) acc[i][j] = fmaf(wv[i], lv[j], acc[i][j]);
        }
        __syncthreads();
    }
#pragma unroll
    for (int i = 0; i < 4; i++) {
        int m = mb * 32 + mg * 4 + i;
        float bias = bpsi[m];
#pragma unroll
        for (int j = 0; j < 4; j++) {
            int t = tb * 64 + tg * 4 + j;
            g_clisT[((size_t)b * MM + m) * TL + t] = fmaxf(acc[i][j] + bias, 0.f);
        }
    }
}

// ---------------------------------------------------------------------------
// GEMM tile 64 rows x 32 batch, 128 threads, 4x4 micro (R2-proven staging).
// out[b*LD + r] = sum_{k in [k0,k1)} W[r][k] * X[b][k]
// ---------------------------------------------------------------------------
__device__ __forceinline__ void gemm64(
        const float* __restrict__ W, int ldw, int mrows,
        const float* __restrict__ X, int ldx,
        int rbase, int k0, int k1, float* __restrict__ out,
        float* Ws, float* Xs) {
    const int tid = threadIdx.x;
    const int rowg = tid >> 3, bg = tid & 7;
    float acc[4][4] = {};
    for (int kc = k0; kc < k1; kc += 32) {
#pragma unroll
        for (int i = 0; i < 16; i++) {           // W: 64 rows x 32 k
            int lin = tid + i * 128;
            int row = lin >> 5, kk = lin & 31;
            int r = rbase + row, k = kc + kk;
            Ws[row * 33 + kk] = (k < k1 && r < mrows) ? W[(size_t)r * ldw + k] : 0.f;
        }
#pragma unroll
        for (int i = 0; i < 8; i++) {            // X: 32 b x 32 k
            int lin = tid + i * 128;
            int bb = lin >> 5, kk = lin & 31;
            int k = kc + kk;
            Xs[bb * 33 + kk] = (k < k1) ? X[(size_t)bb * ldx + k] : 0.f;
        }
        __syncthreads();
#pragma unroll 8
        for (int kk = 0; kk < 32; kk++) {
            float wv[4], xv[4];
#pragma unroll
            for (int i = 0; i < 4; i++) wv[i] = Ws[(rowg * 4 + i) * 33 + kk];
#pragma unroll
            for (int j = 0; j < 4; j++) xv[j] = Xs[(bg * 4 + j) * 33 + kk];
#pragma unroll
            for (int i = 0; i < 4; i++)
#pragma unroll
                for (int j = 0; j < 4; j++) acc[i][j] = fmaf(wv[i], xv[j], acc[i][j]);
        }
        __syncthreads();
    }
#pragma unroll
    for (int i = 0; i < 4; i++) {
        int r = rbase + rowg * 4 + i;
        if (r < mrows)
#pragma unroll
            for (int j = 0; j < 4; j++)
                out[(size_t)(bg * 4 + j) * LD + r] = acc[i][j];
    }
}

// Node A: grid (32, 10), 128 threads.
// y 0..5: Wih0 K-chunks -> g_p0 slots 0..5; y 6,7: Whh0 halves -> slots 6,7;
// y 8,9: Whh1 halves -> g_p1w slots 0,1.
__global__ void __launch_bounds__(128) k_A(
        const float* __restrict__ Wih0, const float* __restrict__ Whh0,
        const float* __restrict__ Whh1) {
    __shared__ float Ws[64 * 33];
    __shared__ float Xs[32 * 33];
    int tile = blockIdx.x, s = blockIdx.y;
    int rbase = tile * 64;
    if (s < 6) {
        int k0 = s * CH_IH0, k1 = min(XD, k0 + CH_IH0);
        gemm64(Wih0, XD, G4, g_x, XD, rbase, k0, k1,
               g_p0 + (size_t)s * BB * LD, Ws, Xs);
    } else if (s < 8) {
        int sl = s - 6;
        gemm64(Whh0, HH, G4, g_h0, HH, rbase, sl * 256, sl * 256 + 256,
               g_p0 + (size_t)s * BB * LD, Ws, Xs);
    } else {
        int sl = s - 8;
        gemm64(Whh1, HH, G4, g_h1, HH, rbase, sl * 256, sl * 256 + 256,
               g_p1w + (size_t)sl * BB * LD, Ws, Xs);
    }
}

// ---------------------------------------------------------------------------
// Node B: fused cell0 + gates1 + cell1. grid 64 = (b, half), 256 threads.
// ---------------------------------------------------------------------------
__global__ void __launch_bounds__(256) k_B(
        const float* __restrict__ bih0, const float* __restrict__ bhh0,
        const float* __restrict__ Wih1,
        const float* __restrict__ bih1, const float* __restrict__ bhh1,
        const float* __restrict__ c0_in, float* __restrict__ c0_out) {
    __shared__ float h0s[HH];
    int b = blockIdx.x >> 1, h = blockIdx.x & 1;
    int tid = threadIdx.x;
    const float* P0b = g_p0 + (size_t)b * LD;          // + s*BB*LD per slot

    // ---- cell0 (redundant across halves; h==0 publishes) ----
#pragma unroll
    for (int jj = tid; jj < HH; jj += 256) {
        float g[4];
#pragma unroll
        for (int gi = 0; gi < 4; gi++) {
            int r = gi * HH + jj;
            float v = bih0[r] + bhh0[r];
#pragma unroll
            for (int s = 0; s < S_P0; s++) v += P0b[(size_t)s * BB * LD + r];
            g[gi] = v;
        }
        float ig = sigmoidf_(g[0]);
        float fg = sigmoidf_(g[1]);
        float gg = tanhf(g[2]);
        float og = sigmoidf_(g[3]);
        float cn = fg * c0_in[b * HH + jj] + ig * gg;
        float hn = og * tanhf(cn);
        if (h == 0) {
            c0_out[b * HH + jj] = cn;
            g_h0[b * HH + jj] = hn;
        }
        h0s[jj] = hn;
    }
    __syncthreads();

    // ---- gates1 rows {g*512 + h*256 + tid} via float4-streamed GEMV ----
    const float* P1b = g_p1w + (size_t)b * LD;
    float acc[4];
    int rows[4];
#pragma unroll
    for (int gi = 0; gi < 4; gi++) {
        int r = gi * HH + h * 256 + tid;
        rows[gi] = r;
        acc[gi] = bih1[r] + bhh1[r] + P1b[r] + P1b[(size_t)BB * LD + r];
    }
    const float4* w0 = (const float4*)(Wih1 + (size_t)rows[0] * HH);
    const float4* w1 = (const float4*)(Wih1 + (size_t)rows[1] * HH);
    const float4* w2 = (const float4*)(Wih1 + (size_t)rows[2] * HH);
    const float4* w3 = (const float4*)(Wih1 + (size_t)rows[3] * HH);
#pragma unroll 4
    for (int k4 = 0; k4 < HH / 4; k4++) {
        float x0 = h0s[k4 * 4 + 0], x1 = h0s[k4 * 4 + 1];
        float x2 = h0s[k4 * 4 + 2], x3 = h0s[k4 * 4 + 3];
        float4 a = w0[k4], bq = w1[k4], cq = w2[k4], dq = w3[k4];
        acc[0] = fmaf(a.x, x0, fmaf(a.y, x1, fmaf(a.z, x2, fmaf(a.w, x3, acc[0]))));
        acc[1] = fmaf(bq.x, x0, fmaf(bq.y, x1, fmaf(bq.z, x2, fmaf(bq.w, x3, acc[1]))));
        acc[2] = fmaf(cq.x, x0, fmaf(cq.y, x1, fmaf(cq.z, x2, fmaf(cq.w, x3, acc[2]))));
        acc[3] = fmaf(dq.x, x0, fmaf(dq.y, x1, fmaf(dq.z, x2, fmaf(dq.w, x3, acc[3]))));
    }

    // ---- cell1 on exclusive j-range ----
    int j = h * 256 + tid;
    float ig = sigmoidf_(acc[0]);
    float fg = sigmoidf_(acc[1]);
    float gg = tanhf(acc[2]);
    float og = sigmoidf_(acc[3]);
    float cn = fg * g_c1[b * HH + j] + ig * gg;
    float hn = og * tanhf(cn);
    g_c1[b * HH + j] = cn;
    g_h1[b * HH + j] = hn;
}

// ---------------------------------------------------------------------------
// GEMM tile 128 rows x 32 batch, 256 threads, 4x4 micro.
// out[b*LD + r] = sum_k W[r][k] * X[b][k]
// ---------------------------------------------------------------------------
__device__ __forceinline__ void gemm128(
        const float* __restrict__ W, int ldw, int mrows,
        const float* __restrict__ X, int ldx,
        int rbase, int k0, int k1, float* __restrict__ out,
        float* Ws, float* Xs) {
    const int tid = threadIdx.x;
    const int rowg = tid >> 3, bg = tid & 7;
    float acc[4][4] = {};
    for (int kc = k0; kc < k1; kc += 32) {
#pragma unroll
        for (int i = 0; i < 16; i++) {           // W: 128 rows x 32 k
            int lin = tid + i * 256;
            int row = lin >> 5, kk = lin & 31;
            int r = rbase + row, k = kc + kk;
            Ws[row * 33 + kk] = (k < k1 && r < mrows) ? W[(size_t)r * ldw + k] : 0.f;
        }
#pragma unroll
        for (int i = 0; i < 4; i++) {            // X: 32 b x 32 k
            int lin = tid + i * 256;
            int bb = lin >> 5, kk = lin & 31;
            int k = kc + kk;
            Xs[bb * 33 + kk] = (k < k1) ? X[(size_t)bb * ldx + k] : 0.f;
        }
        __syncthreads();
#pragma unroll 8
        for (int kk = 0; kk < 32; kk++) {
            float wv[4], xv[4];
#pragma unroll
            for (int i = 0; i < 4; i++) wv[i] = Ws[(rowg * 4 + i) * 33 + kk];
#pragma unroll
            for (int j = 0; j < 4; j++) xv[j] = Xs[(bg * 4 + j) * 33 + kk];
#pragma unroll
            for (int i = 0; i < 4; i++)
#pragma unroll
                for (int j = 0; j < 4; j++) acc[i][j] = fmaf(wv[i], xv[j], acc[i][j]);
        }
        __syncthreads();
    }
#pragma unroll
    for (int i = 0; i < 4; i++) {
        int r = rbase + rowg * 4 + i;
        if (r < mrows)
#pragma unroll
            for (int j = 0; j < 4; j++)
                out[(size_t)(bg * 4 + j) * LD + r] = acc[i][j];
    }
}

// ---------------------------------------------------------------------------
// Node C: blocks 0..31 attention (phi fused); blocks 32..63 logits h1-half.
// 256 threads.
// ---------------------------------------------------------------------------
__global__ void __launch_bounds__(256) k_C(
        const float* __restrict__ lis,
        const float* __restrict__ Wphi, const float* __restrict__ bphi,
        const float* __restrict__ Wc,
        float* __restrict__ attn_out) {
    __shared__ float smem[128 * 33 + 32 * 33];
    int blk = blockIdx.x, tid = threadIdx.x;
    if (blk >= 32) {
        int u = blk - 32;               // 16 tiles x 2 K-slots
        int tile = u >> 1, slot = u & 1;
        gemm128(Wc, 2 * HH, VV, g_h1, HH, tile * 128,
                slot * 256, slot * 256 + 256,
                g_pl + (size_t)slot * BB * LD,
                smem, smem + 128 * 33);
        return;
    }
    // ---- attention for batch blk ----
    float* h1s = smem;            // 512
    float* cd  = smem + 512;      // 256
    float* av  = smem + 768;      // 256
    float* rb  = smem + 1024;     // 256
    int b = blk;
    for (int i = tid; i < HH; i += 256) h1s[i] = g_h1[(size_t)b * HH + i];
    __syncthreads();
    int warp = tid >> 5, lane = tid & 31;
    for (int m = warp; m < MM; m += 8) {
        const float* w = Wphi + (size_t)m * HH;
        float p = 0.f;
#pragma unroll 4
        for (int k = lane; k < HH; k += 32) p = fmaf(w[k], h1s[k], p);
#pragma unroll
        for (int o = 16; o; o >>= 1) p += __shfl_down_sync(0xffffffffu, p, o);
        if (lane == 0) cd[m] = fmaxf(p + bphi[m], 0.f);
    }
    __syncthreads();
    const float* cl = g_clisT + (size_t)b * MM * TL + tid;
    float e = 0.f;
#pragma unroll 8
    for (int m = 0; m < MM; m++) e = fmaf(cd[m], cl[(size_t)m * TL], e);
    rb[tid] = e; __syncthreads();
    for (int o = 128; o > 0; o >>= 1) { if (tid < o) rb[tid] = fmaxf(rb[tid], rb[tid + o]); __syncthreads(); }
    float mx = rb[0]; __syncthreads();
    float p = expf(e - mx);
    rb[tid] = p; __syncthreads();
    for (int o = 128; o > 0; o >>= 1) { if (tid < o) rb[tid] += rb[tid + o]; __syncthreads(); }
    float a = p / rb[0];
    av[tid] = a;
    attn_out[(size_t)b * TL + tid] = a;
    __syncthreads();
    const float* lb = lis + (size_t)b * TL * DL;
#pragma unroll
    for (int dd = 0; dd < 2; dd++) {
        int d = tid + dd * 256;
        float cx = 0.f;
#pragma unroll 4
        for (int t = 0; t < TL; t++) cx = fmaf(av[t], lb[(size_t)t * DL + d], cx);
        g_ctx[(size_t)b * HH + d] = cx;
        g_x[(size_t)b * XD + VV + d] = cx;
    }
}

// Node D: logits ctx-half. grid 32 = 16 tiles x 2 K-slots, 256 threads.
__global__ void __launch_bounds__(256) k_D(const float* __restrict__ Wc) {
    __shared__ float smem[128 * 33 + 32 * 33];
    int u = blockIdx.x;
    int tile = u >> 1, slot = u & 1;
    gemm128(Wc + HH, 2 * HH, VV, g_ctx, HH, tile * 128,
            slot * 256, slot * 256 + 256,
            g_pl + (size_t)(2 + slot) * BB * LD,
            smem, smem + 128 * 33);
}

// ---------------------------------------------------------------------------
// Node E: log-softmax + feedback. grid 32 (per batch), 256 threads.
// ---------------------------------------------------------------------------
__global__ void __launch_bounds__(256) k_E(
        const float* __restrict__ bc, float* __restrict__ preds_out) {
    __shared__ float lg[2048];
    __shared__ float rb[256];
    int b = blockIdx.x, tid = threadIdx.x;
    const float* Pb = g_pl + (size_t)b * LD;
    float lmax = -1e30f;
    for (int v = tid; v < VV; v += 256) {
        float x = bc[v];
#pragma unroll
        for (int s = 0; s < 4; s++) x += Pb[(size_t)s * BB * LD + v];
        lg[v] = x;
        lmax = fmaxf(lmax, x);
    }
    rb[tid] = lmax; __syncthreads();
    for (int o = 128; o > 0; o >>= 1) { if (tid < o) rb[tid] = fmaxf(rb[tid], rb[tid + o]); __syncthreads(); }
    float mx = rb[0]; __syncthreads();
    float s = 0.f;
    for (int v = tid; v < VV; v += 256) s += expf(lg[v] - mx);
    rb[tid] = s; __syncthreads();
    for (int o = 128; o > 0; o >>= 1) { if (tid < o) rb[tid] += rb[tid + o]; __syncthreads(); }
    float lse = mx + logf(rb[0]);
    for (int v = tid; v < VV; v += 256) {
        float r = lg[v] - lse;
        preds_out[(size_t)b * VV + v] = r;
        g_x[(size_t)b * XD + v] = r;
    }
}

// ---------------------------------------------------------------------------
// Launcher: graph-capturable, deterministic, allocation-free.
// ---------------------------------------------------------------------------
extern "C" void kernel_launch(void* const* d_in, const int* in_sizes, int n_in,
                              void* d_out, int out_size) {
    const float* lis  = (const float*)d_in[0];
    const float* Wih0 = (const float*)d_in[1];
    const float* Whh0 = (const float*)d_in[2];
    const float* bih0 = (const float*)d_in[3];
    const float* bhh0 = (const float*)d_in[4];
    const float* Wih1 = (const float*)d_in[5];
    const float* Whh1 = (const float*)d_in[6];
    const float* bih1 = (const float*)d_in[7];
    const float* bhh1 = (const float*)d_in[8];
    const float* Wphi = (const float*)d_in[9];
    const float* bphi = (const float*)d_in[10];
    const float* Wpsi = (const float*)d_in[11];
    const float* bpsi = (const float*)d_in[12];
    const float* Wc   = (const float*)d_in[13];
    const float* bc   = (const float*)d_in[14];

    float* preds = (float*)d_out;                      // [100,32,2000]
    float* attns = preds + (size_t)NSTEP * BB * VV;    // [100,32,256]

    float *c0a, *c0b;
    cudaGetSymbolAddress((void**)&c0a, g_c0a);
    cudaGetSymbolAddress((void**)&c0b, g_c0b);

    k_init<<<(BB * XD + 255) / 256, 256>>>(lis);
    k_psi<<<dim3(8, 4, BB), 128>>>(lis, Wpsi, bpsi);

    for (int t = 0; t < NSTEP; t++) {
        float* ci = (t & 1) ? c0b : c0a;
        float* co = (t & 1) ? c0a : c0b;
        // A: gates0 partials + Whh1@h1_prev  (320 blocks)
        k_A<<<dim3(32, 10), 128>>>(Wih0, Whh0, Whh1);
        // B: cell0 + gates1 + cell1          (64 blocks)
        k_B<<<64, 256>>>(bih0, bhh0, Wih1, bih1, bhh1, ci, co);
        // C: attention || logits h1-half     (64 blocks)
        k_C<<<64, 256>>>(lis, Wphi, bphi, Wc, attns + (size_t)t * BB * TL);
        // D: logits ctx-half                 (32 blocks)
        k_D<<<32, 256>>>(Wc);
        // E: log-softmax + feedback          (32 blocks)
        k_E<<<32, 256>>>(bc, preds + (size_t)t * BB * VV);
    }
}

// round 12
// speedup vs baseline: 1.4674x; 1.4674x over previous
#include <cuda_runtime.h>
#include <math.h>

#define BB 32
#define TL 256
#define DL 512
#define HH 512
#define VV 2000
#define MM 256
#define G4 2048
#define XD 2512
#define NSTEP 100
#define LD 2048          // row stride inside partial buffers

#define CH_IH0 314       // 8 * 314 == 2512 exactly
#define S_P0  12         // 8 (Wih0) + 4 (Whh0)
#define S_P1  8          // 4 (Whh1) + 4 (Wih1)
#define S_PL  8          // 4 (h1 half) + 4 (ctx half)

// ---------------- persistent device state ----------------
__device__ float g_x[BB * XD];
__device__ float g_h0[BB * HH], g_h1[BB * HH];
__device__ float g_c0[BB * HH], g_c1[BB * HH];
__device__ float g_ctx[BB * HH];
__device__ float g_p0[(size_t)S_P0 * BB * LD];   // [s][b][r]
__device__ float g_p1[(size_t)S_P1 * BB * LD];
__device__ float g_pl[(size_t)S_PL * BB * LD];
__device__ float g_clisT[(size_t)BB * MM * TL];  // [b][m][t]

__device__ __forceinline__ float sigmoidf_(float x) { return 1.f / (1.f + expf(-x)); }

// PDL entry gate: all predecessor writes visible after this returns.
__device__ __forceinline__ void gds() {
#if __CUDA_ARCH__ >= 900
    cudaGridDependencySynchronize();
#endif
}

// ---------------------------------------------------------------------------
// init: x0 = [onehot(0), listener[:,0,:]]; zero states
// ---------------------------------------------------------------------------
__global__ void k_init(const float* __restrict__ lis) {
    gds();
    int i = blockIdx.x * blockDim.x + threadIdx.x;
    if (i < BB * XD) {
        int b = i / XD, k = i % XD;
        float v = 0.f;
        if (k == 0) v = 1.f;
        else if (k >= VV) v = lis[(size_t)b * TL * DL + (k - VV)];
        g_x[i] = v;
    }
    if (i < BB * HH) {
        g_h0[i] = 0.f; g_h1[i] = 0.f;
        g_c0[i] = 0.f; g_c1[i] = 0.f;
    }
}

// ---------------------------------------------------------------------------
// one-time psi: clisT[b][m][t] = relu(lis[b][t].Wpsi[m]+bpsi[m])
// ---------------------------------------------------------------------------
__global__ void k_psi(const float* __restrict__ lis,
                      const float* __restrict__ Wpsi,
                      const float* __restrict__ bpsi) {
    gds();
    int mb = blockIdx.x, tb = blockIdx.y, b = blockIdx.z;
    int tid = threadIdx.x;
    int mg = tid >> 4, tg = tid & 15;
    __shared__ float Ws[32 * 33];
    __shared__ float Ls[64 * 33];
    float acc[4][4] = {};
    const float* lb = lis + (size_t)b * TL * DL;
    for (int kc = 0; kc < DL; kc += 32) {
#pragma unroll
        for (int i = 0; i < 8; i++) {
            int lin = tid + i * 128;
            int row = lin >> 5, kk = lin & 31;
            Ws[row * 33 + kk] = Wpsi[(size_t)(mb * 32 + row) * DL + kc + kk];
        }
#pragma unroll
        for (int i = 0; i < 16; i++) {
            int lin = tid + i * 128;
            int row = lin >> 5, kk = lin & 31;
            Ls[row * 33 + kk] = lb[(size_t)(tb * 64 + row) * DL + kc + kk];
        }
        __syncthreads();
#pragma unroll 8
        for (int kk = 0; kk < 32; kk++) {
            float wv[4], lv[4];
#pragma unroll
            for (int i = 0; i < 4; i++) wv[i] = Ws[(mg * 4 + i) * 33 + kk];
#pragma unroll
            for (int j = 0; j < 4; j++) lv[j] = Ls[(tg * 4 + j) * 33 + kk];
#pragma unroll
            for (int i = 0; i < 4; i++)
#pragma unroll
                for (int j = 0; j < 4; j++) acc[i][j] = fmaf(wv[i], lv[j], acc[i][j]);
        }
        __syncthreads();
    }
#pragma unroll
    for (int i = 0; i < 4; i++) {
        int m = mb * 32 + mg * 4 + i;
        float bias = bpsi[m];
#pragma unroll
        for (int j = 0; j < 4; j++) {
            int t = tb * 64 + tg * 4 + j;
            g_clisT[((size_t)b * MM + m) * TL + t] = fmaxf(acc[i][j] + bias, 0.f);
        }
    }
}

// ---------------------------------------------------------------------------
// GEMM tile 64 rows x 32 batch, 128 threads, 4x4 micro (validated R2/R11).
// out[b*LD + r] = sum_{k in [k0,k1)} W[r][k] * X[b][k]
// ---------------------------------------------------------------------------
__device__ __forceinline__ void gemm64(
        const float* __restrict__ W, int ldw, int mrows,
        const float* __restrict__ X, int ldx,
        int rbase, int k0, int k1, float* __restrict__ out) {
    __shared__ float Ws[64 * 33];
    __shared__ float Xs[32 * 33];
    const int tid = threadIdx.x;
    const int rowg = tid >> 3, bg = tid & 7;
    float acc[4][4] = {};
    for (int kc = k0; kc < k1; kc += 32) {
#pragma unroll
        for (int i = 0; i < 16; i++) {           // W: 64 rows x 32 k
            int lin = tid + i * 128;
            int row = lin >> 5, kk = lin & 31;
            int r = rbase + row, k = kc + kk;
            Ws[row * 33 + kk] = (k < k1 && r < mrows) ? W[(size_t)r * ldw + k] : 0.f;
        }
#pragma unroll
        for (int i = 0; i < 8; i++) {            // X: 32 b x 32 k
            int lin = tid + i * 128;
            int bb = lin >> 5, kk = lin & 31;
            int k = kc + kk;
            Xs[bb * 33 + kk] = (k < k1) ? X[(size_t)bb * ldx + k] : 0.f;
        }
        __syncthreads();
#pragma unroll 8
        for (int kk = 0; kk < 32; kk++) {
            float wv[4], xv[4];
#pragma unroll
            for (int i = 0; i < 4; i++) wv[i] = Ws[(rowg * 4 + i) * 33 + kk];
#pragma unroll
            for (int j = 0; j < 4; j++) xv[j] = Xs[(bg * 4 + j) * 33 + kk];
#pragma unroll
            for (int i = 0; i < 4; i++)
#pragma unroll
                for (int j = 0; j < 4; j++) acc[i][j] = fmaf(wv[i], xv[j], acc[i][j]);
        }
        __syncthreads();
    }
#pragma unroll
    for (int i = 0; i < 4; i++) {
        int r = rbase + rowg * 4 + i;
        if (r < mrows)
#pragma unroll
            for (int j = 0; j < 4; j++)
                out[(size_t)(bg * 4 + j) * LD + r] = acc[i][j];
    }
}

// Node A: gates0 (Wih0@x + Whh0@h0) and Whh1@h1_prev.
// grid (32, 16): y<8 Wih0 slots, y in [8,12) Whh0, y in [12,16) Whh1.
__global__ void __launch_bounds__(128) k_A(
        const float* __restrict__ Wih0, const float* __restrict__ Whh0,
        const float* __restrict__ Whh1) {
    gds();
    int tile = blockIdx.x, s = blockIdx.y;
    if (s < 8) {
        int k0 = s * CH_IH0;
        gemm64(Wih0, XD, G4, g_x, XD, tile * 64, k0, k0 + CH_IH0,
               g_p0 + (size_t)s * BB * LD);
    } else if (s < 12) {
        int sl = s - 8;
        gemm64(Whh0, HH, G4, g_h0, HH, tile * 64, sl * 128, sl * 128 + 128,
               g_p0 + (size_t)(8 + sl) * BB * LD);
    } else {
        int sl = s - 12;
        gemm64(Whh1, HH, G4, g_h1, HH, tile * 64, sl * 128, sl * 128 + 128,
               g_p1 + (size_t)sl * BB * LD);
    }
}

// Node C: Wih1 @ h0_new. grid (32, 4) -> g_p1 slots 4..7.
__global__ void __launch_bounds__(128) k_C(const float* __restrict__ Wih1) {
    gds();
    int tile = blockIdx.x, s = blockIdx.y;
    gemm64(Wih1, HH, G4, g_h0, HH, tile * 64, s * 128, s * 128 + 128,
           g_p1 + (size_t)(4 + s) * BB * LD);
}

// Node F: logits ctx-half. grid (32, 4) -> g_pl slots 4..7.
__global__ void __launch_bounds__(128) k_F(const float* __restrict__ Wc) {
    gds();
    int tile = blockIdx.x, s = blockIdx.y;
    gemm64(Wc + HH, 2 * HH, VV, g_ctx, HH, tile * 64, s * 128, s * 128 + 128,
           g_pl + (size_t)(4 + s) * BB * LD);
}

// ---------------------------------------------------------------------------
// LSTM cells: 64 blocks x 256 thr, one (b,j) each; coalesced [s][b][r] reads.
// ---------------------------------------------------------------------------
template <int NS>
__global__ void __launch_bounds__(256) k_cell(
        const float* __restrict__ P,
        const float* __restrict__ bih, const float* __restrict__ bhh,
        float* __restrict__ h, float* __restrict__ c) {
    gds();
    int idx = blockIdx.x * 256 + threadIdx.x;    // 0..16383
    int b = idx >> 9, j = idx & 511;
    const float* Pb = P + (size_t)b * LD;
    float g[4];
#pragma unroll
    for (int gi = 0; gi < 4; gi++) {
        int r = gi * HH + j;
        float v = bih[r] + bhh[r];
#pragma unroll
        for (int s = 0; s < NS; s++) v += Pb[(size_t)s * BB * LD + r];
        g[gi] = v;
    }
    float ig = sigmoidf_(g[0]);
    float fg = sigmoidf_(g[1]);
    float gg = tanhf(g[2]);
    float og = sigmoidf_(g[3]);
    float cn = fg * c[b * HH + j] + ig * gg;
    float hn = og * tanhf(cn);
    c[b * HH + j] = cn;
    h[b * HH + j] = hn;
}

// ---------------------------------------------------------------------------
// Node E: blocks 0..31 attention (phi fused); blocks 32..159 logits h1-half.
// ---------------------------------------------------------------------------
__global__ void __launch_bounds__(256) k_E(
        const float* __restrict__ lis,
        const float* __restrict__ Wphi, const float* __restrict__ bphi,
        const float* __restrict__ Wc,
        float* __restrict__ attn_out) {
    gds();
    int blk = blockIdx.x, tid = threadIdx.x;
    if (blk >= 32) {
        // logits h1-half: 32 tiles x 4 K-slots, 2 blocks' worth of threads each?
        // 128 blocks: u = blk-32; tile = u >> 2, slot = u & 3. 256 threads run
        // the 128-thread gemm64 body? No — gemm64 expects 128 threads. Split:
        // use only the first 128 threads of the block.
        if (tid < 128) {
            // re-enter a 128-thread gemm on a sub-block is invalid due to
            // __syncthreads scope; instead all 256 threads cooperate below.
        }
        // 256-thread variant of the 64x32 tile: same staging, 2x rows per pass.
        {
            __shared__ float Ws[64 * 33];
            __shared__ float Xs[32 * 33];
            int u = blk - 32;
            int tile = u >> 2, slot = u & 3;
            int rbase = tile * 64;
            int k0 = slot * 128, k1 = k0 + 128;
            const float* W = Wc;            // h1 half: columns [0,512)
            const float* X = g_h1;
            float* out = g_pl + (size_t)slot * BB * LD;
            int rowg = tid >> 3, bg = tid & 7;     // 32 row-groups x 8 b-groups
            float acc[2][4] = {};
            for (int kc = k0; kc < k1; kc += 32) {
#pragma unroll
                for (int i = 0; i < 8; i++) {      // W: 64 rows x 32 k
                    int lin = tid + i * 256;
                    int row = lin >> 5, kk = lin & 31;
                    int r = rbase + row;
                    Ws[row * 33 + kk] = (r < VV) ? W[(size_t)r * (2 * HH) + kc + kk] : 0.f;
                }
#pragma unroll
                for (int i = 0; i < 4; i++) {      // X: 32 b x 32 k
                    int lin = tid + i * 256;
                    int bb = lin >> 5, kk = lin & 31;
                    Xs[bb * 33 + kk] = X[(size_t)bb * HH + kc + kk];
                }
                __syncthreads();
#pragma unroll 8
                for (int kk = 0; kk < 32; kk++) {
                    float xv[4];
#pragma unroll
                    for (int j = 0; j < 4; j++) xv[j] = Xs[(bg * 4 + j) * 33 + kk];
#pragma unroll
                    for (int i = 0; i < 2; i++) {
                        float wv = Ws[(rowg * 2 + i) * 33 + kk];
#pragma unroll
                        for (int j = 0; j < 4; j++)
                            acc[i][j] = fmaf(wv, xv[j], acc[i][j]);
                    }
                }
                __syncthreads();
            }
#pragma unroll
            for (int i = 0; i < 2; i++) {
                int r = rbase + rowg * 2 + i;
                if (r < VV)
#pragma unroll
                    for (int j = 0; j < 4; j++)
                        out[(size_t)(bg * 4 + j) * LD + r] = acc[i][j];
            }
        }
        return;
    }
    // ---- attention for batch blk ----
    __shared__ float h1s[HH];
    __shared__ float cd[MM];
    __shared__ float av[TL];
    __shared__ float rb[TL];
    int b = blk;
    for (int i = tid; i < HH; i += 256) h1s[i] = g_h1[(size_t)b * HH + i];
    __syncthreads();
    int warp = tid >> 5, lane = tid & 31;
    for (int m = warp; m < MM; m += 8) {
        const float* w = Wphi + (size_t)m * HH;
        float p = 0.f;
#pragma unroll 4
        for (int k = lane; k < HH; k += 32) p = fmaf(w[k], h1s[k], p);
#pragma unroll
        for (int o = 16; o; o >>= 1) p += __shfl_down_sync(0xffffffffu, p, o);
        if (lane == 0) cd[m] = fmaxf(p + bphi[m], 0.f);
    }
    __syncthreads();
    const float* cl = g_clisT + (size_t)b * MM * TL + tid;
    float e = 0.f;
#pragma unroll 8
    for (int m = 0; m < MM; m++) e = fmaf(cd[m], cl[(size_t)m * TL], e);
    rb[tid] = e; __syncthreads();
    for (int o = 128; o > 0; o >>= 1) { if (tid < o) rb[tid] = fmaxf(rb[tid], rb[tid + o]); __syncthreads(); }
    float mx = rb[0]; __syncthreads();
    float p = expf(e - mx);
    rb[tid] = p; __syncthreads();
    for (int o = 128; o > 0; o >>= 1) { if (tid < o) rb[tid] += rb[tid + o]; __syncthreads(); }
    float a = p / rb[0];
    av[tid] = a;
    attn_out[(size_t)b * TL + tid] = a;
    __syncthreads();
    const float* lb = lis + (size_t)b * TL * DL;
#pragma unroll
    for (int dd = 0; dd < 2; dd++) {
        int d = tid + dd * 256;
        float cx = 0.f;
#pragma unroll 4
        for (int t = 0; t < TL; t++) cx = fmaf(av[t], lb[(size_t)t * DL + d], cx);
        g_ctx[(size_t)b * HH + d] = cx;
        g_x[(size_t)b * XD + VV + d] = cx;
    }
}

// ---------------------------------------------------------------------------
// Node G: log-softmax + feedback. grid 32 (per batch), 256 threads.
// ---------------------------------------------------------------------------
__global__ void __launch_bounds__(256) k_G(
        const float* __restrict__ bc, float* __restrict__ preds_out) {
    gds();
    __shared__ float lg[2048];
    __shared__ float rb[256];
    int b = blockIdx.x, tid = threadIdx.x;
    const float* Pb = g_pl + (size_t)b * LD;
    float lmax = -1e30f;
    for (int v = tid; v < VV; v += 256) {
        float x = bc[v];
#pragma unroll
        for (int s = 0; s < S_PL; s++) x += Pb[(size_t)s * BB * LD + v];
        lg[v] = x;
        lmax = fmaxf(lmax, x);
    }
    rb[tid] = lmax; __syncthreads();
    for (int o = 128; o > 0; o >>= 1) { if (tid < o) rb[tid] = fmaxf(rb[tid], rb[tid + o]); __syncthreads(); }
    float mx = rb[0]; __syncthreads();
    float s = 0.f;
    for (int v = tid; v < VV; v += 256) s += expf(lg[v] - mx);
    rb[tid] = s; __syncthreads();
    for (int o = 128; o > 0; o >>= 1) { if (tid < o) rb[tid] += rb[tid + o]; __syncthreads(); }
    float lse = mx + logf(rb[0]);
    for (int v = tid; v < VV; v += 256) {
        float r = lg[v] - lse;
        preds_out[(size_t)b * VV + v] = r;
        g_x[(size_t)b * XD + v] = r;
    }
}

// ---------------------------------------------------------------------------
// PDL launch helper (no streams/events/allocations; graph-capturable).
// ---------------------------------------------------------------------------
template <typename F, typename... Args>
static inline void pdl_launch(F f, dim3 grid, dim3 block, Args... args) {
    cudaLaunchConfig_t cfg = {};
    cudaLaunchAttribute attr[1];
    cfg.gridDim = grid;
    cfg.blockDim = block;
    cfg.dynamicSmemBytes = 0;
    cfg.stream = 0;
    attr[0].id = cudaLaunchAttributeProgrammaticStreamSerialization;
    attr[0].val.programmaticStreamSerializationAllowed = 1;
    cfg.attrs = attr;
    cfg.numAttrs = 1;
    cudaLaunchKernelEx(&cfg, f, args...);
}

// ---------------------------------------------------------------------------
// Launcher: single-stream PDL chain, graph-capturable, allocation-free.
// ---------------------------------------------------------------------------
extern "C" void kernel_launch(void* const* d_in, const int* in_sizes, int n_in,
                              void* d_out, int out_size) {
    const float* lis  = (const float*)d_in[0];
    const float* Wih0 = (const float*)d_in[1];
    const float* Whh0 = (const float*)d_in[2];
    const float* bih0 = (const float*)d_in[3];
    const float* bhh0 = (const float*)d_in[4];
    const float* Wih1 = (const float*)d_in[5];
    const float* Whh1 = (const float*)d_in[6];
    const float* bih1 = (const float*)d_in[7];
    const float* bhh1 = (const float*)d_in[8];
    const float* Wphi = (const float*)d_in[9];
    const float* bphi = (const float*)d_in[10];
    const float* Wpsi = (const float*)d_in[11];
    const float* bpsi = (const float*)d_in[12];
    const float* Wc   = (const float*)d_in[13];
    const float* bc   = (const float*)d_in[14];

    float* preds = (float*)d_out;                      // [100,32,2000]
    float* attns = preds + (size_t)NSTEP * BB * VV;    // [100,32,256]

    float *p0, *p1, *h0, *h1, *c0, *c1;
    cudaGetSymbolAddress((void**)&p0, g_p0);
    cudaGetSymbolAddress((void**)&p1, g_p1);
    cudaGetSymbolAddress((void**)&h0, g_h0);
    cudaGetSymbolAddress((void**)&h1, g_h1);
    cudaGetSymbolAddress((void**)&c0, g_c0);
    cudaGetSymbolAddress((void**)&c1, g_c1);

    pdl_launch(k_init, dim3((BB * XD + 255) / 256), dim3(256), lis);
    pdl_launch(k_psi, dim3(8, 4, BB), dim3(128), lis, Wpsi, bpsi);

    for (int t = 0; t < NSTEP; t++) {
        // A: gates0 partials + Whh1@h1_prev   (512 blocks)
        pdl_launch(k_A, dim3(32, 16), dim3(128), Wih0, Whh0, Whh1);
        // B: cell0
        pdl_launch(k_cell<S_P0>, dim3(64), dim3(256), (const float*)p0,
                   bih0, bhh0, h0, c0);
        // C: Wih1 @ h0_new
        pdl_launch(k_C, dim3(32, 4), dim3(128), Wih1);
        // D: cell1
        pdl_launch(k_cell<S_P1>, dim3(64), dim3(256), (const float*)p1,
                   bih1, bhh1, h1, c1);
        // E: attention || logits h1-half       (160 blocks)
        pdl_launch(k_E, dim3(160), dim3(256), lis, Wphi, bphi, Wc,
                   attns + (size_t)t * BB * TL);
        // F: logits ctx-half
        pdl_launch(k_F, dim3(32, 4), dim3(128), Wc);
        // G: log-softmax + feedback
        pdl_launch(k_G, dim3(32), dim3(256), bc, preds + (size_t)t * BB * VV);
    }
}